// round 11
// baseline (speedup 1.0000x reference)
#include <cuda_runtime.h>
#include <cuda_bf16.h>
#include <cstdint>

#define NN 50000
#define DIMX 128
#define NE 800000

// ---- scratch (static __device__ globals; zero-initialized at load) ----
__device__ __nv_bfloat16 g_hb16[2][NN * DIMX];   // ping-pong hidden states (bf16)
__device__ __nv_bfloat16 g_aggb16[NN * DIMX];    // aggregation (bf16)
__device__ uint8_t g_Wf8[3 * 2 * DIMX * DIMX];   // weights e4m3, pre-scaled x64
__device__ int   g_off[NN + 1];
__device__ int   g_cnt[NN];     // degree counters; invariant: zero at launch entry
__device__ int   g_srt[NE];
__device__ int   g_bsum[64];
__device__ float g_ro_all[4][DIMX];   // readout per layer
__device__ unsigned g_hmax[3];        // max|h| per layer, fp32 bits (>=0)

// ================= helpers =================

__device__ __forceinline__ uint32_t smem_u32(const void* p) {
    uint32_t a;
    asm("{ .reg .u64 t; cvta.to.shared.u64 t, %1; cvt.u32.u64 %0, t; }"
        : "=r"(a) : "l"(p));
    return a;
}

__device__ __forceinline__ void ldm_x4(uint32_t* r, uint32_t addr) {
    asm volatile("ldmatrix.sync.aligned.m8n8.x4.shared.b16 {%0,%1,%2,%3}, [%4];"
                 : "=r"(r[0]), "=r"(r[1]), "=r"(r[2]), "=r"(r[3]) : "r"(addr));
}

// e4m3 QMMA: fragment bytes are layout-identical to bf16 HMMA (2 fp8 per 16b slot)
__device__ __forceinline__ void mma_fp8(float* c, const uint32_t* a,
                                        const uint32_t* b) {
    asm volatile(
        "mma.sync.aligned.m16n8k32.row.col.f32.e4m3.e4m3.f32 "
        "{%0,%1,%2,%3}, {%4,%5,%6,%7}, {%8,%9}, {%0,%1,%2,%3};"
        : "+f"(c[0]), "+f"(c[1]), "+f"(c[2]), "+f"(c[3])
        : "r"(a[0]), "r"(a[1]), "r"(a[2]), "r"(a[3]), "r"(b[0]), "r"(b[1]));
}

__device__ __forceinline__ void cp16(uint32_t dst, const void* src) {
    asm volatile("cp.async.cg.shared.global [%0], [%1], 16;"
                 :: "r"(dst), "l"(src) : "memory");
}
#define CP_COMMIT() asm volatile("cp.async.commit_group;" ::: "memory")
#define CP_WAIT(N)  asm volatile("cp.async.wait_group %0;" :: "n"(N) : "memory")

__device__ __forceinline__ void acc_bf2(float& a0, float& a1, uint32_t w) {
    a0 += __uint_as_float(w << 16);
    a1 += __uint_as_float(w & 0xffff0000u);
}

__device__ __forceinline__ uint32_t pack_bf2(float lo, float hi) {
    uint32_t r;
    asm("cvt.rn.bf16x2.f32 %0, %1, %2;" : "=r"(r) : "f"(hi), "f"(lo));
    return r;
}

// pack two f32 into one e4m3x2 halfword (byte0 = lo)
__device__ __forceinline__ uint16_t pack_f8x2(float lo, float hi) {
    uint16_t r;
    asm("cvt.rn.satfinite.e4m3x2.f32 %0, %1, %2;" : "=h"(r) : "f"(hi), "f"(lo));
    return r;
}

__device__ __forceinline__ uint32_t pack_f8x4(float f0, float f1, float f2,
                                              float f3) {
    return (uint32_t)pack_f8x2(f0, f1) | ((uint32_t)pack_f8x2(f2, f3) << 16);
}

// ====== setup: copy_x + W->fp8 + hist + zero ro/hmax + g_off[n] ======

__global__ void setup_kernel(const float* __restrict__ x,
                             const float* __restrict__ Vw,
                             const float* __restrict__ Aw,
                             const int* __restrict__ dst,
                             int n2, int n, int e) {
    int i = blockIdx.x * blockDim.x + threadIdx.x;
    if (i < n2) {
        float2 v = reinterpret_cast<const float2*>(x)[i];
        reinterpret_cast<uint32_t*>(g_hb16[0])[i] = pack_bf2(v.x, v.y);
    }
    if (i < 3 * 16384) {   // 49152 fp8 pairs = 98304 weights
        int el2 = i * 2;
        int l = el2 >> 15;
        int rem = el2 & 32767;
        int phase = rem >> 14;
        int el = rem & 16383;
        const float* W = phase ? Aw : Vw;
        float a = W[l * 16384 + el] * 64.0f;
        float b = W[l * 16384 + el + 1] * 64.0f;
        reinterpret_cast<uint16_t*>(g_Wf8)[i] = pack_f8x2(a, b);
    }
    if (i < e) atomicAdd(&g_cnt[dst[i]], 1);   // g_cnt zero on entry (invariant)
    if (i < 4 * DIMX) ((float*)g_ro_all)[i] = 0.0f;
    if (i < 3) g_hmax[i] = 0u;
    if (i == 0) g_off[n] = e;
}

// ================= CSR build =================

__global__ void scan1_kernel(int n) {
    __shared__ int s[1024];
    int i = blockIdx.x * 1024 + threadIdx.x;
    int v = (i < n) ? g_cnt[i] : 0;
    s[threadIdx.x] = v;
    __syncthreads();
    for (int off = 1; off < 1024; off <<= 1) {
        int t = (threadIdx.x >= off) ? s[threadIdx.x - off] : 0;
        __syncthreads();
        s[threadIdx.x] += t;
        __syncthreads();
    }
    if (i < n) g_off[i] = s[threadIdx.x] - v;
    if (threadIdx.x == 1023) g_bsum[blockIdx.x] = s[1023];
}

__global__ void scan3_kernel(int n) {
    __shared__ int spre[2];
    int tid = threadIdx.x;
    if (tid < 64) {
        int v = (tid < blockIdx.x) ? g_bsum[tid] : 0;
#pragma unroll
        for (int o = 16; o; o >>= 1) v += __shfl_xor_sync(0xffffffffu, v, o);
        if ((tid & 31) == 0) spre[tid >> 5] = v;
    }
    __syncthreads();
    int pre = spre[0] + spre[1];
    int i = blockIdx.x * 1024 + tid;
    if (i < n) g_off[i] += pre;
}

__global__ void scatter_kernel(const int* __restrict__ src,
                               const int* __restrict__ dst, int e) {
    int i = blockIdx.x * blockDim.x + threadIdx.x;
    if (i < e) {
        int d = dst[i];
        int pos = g_off[d] + atomicAdd(&g_cnt[d], -1) - 1;
        g_srt[pos] = src[i];
    }
}

// ============ readout + max|x| of layer-0 input ============

__global__ void readout0_kernel(int n) {
    __shared__ float smax[4];
    const __nv_bfloat16* __restrict__ h = g_hb16[0];
    int j = threadIdx.x;  // 128
    float s = 0.0f, m = 0.0f;
    for (int i = blockIdx.x; i < n; i += gridDim.x) {
        float v = __bfloat162float(h[i * DIMX + j]);
        s += v;
        m = fmaxf(m, fabsf(v));
    }
    atomicAdd(&g_ro_all[0][j], s);
#pragma unroll
    for (int o = 16; o; o >>= 1)
        m = fmaxf(m, __shfl_xor_sync(0xffffffffu, m, o));
    if ((j & 31) == 0) smax[j >> 5] = m;
    __syncthreads();
    if (j == 0) {
        m = fmaxf(fmaxf(smax[0], smax[1]), fmaxf(smax[2], smax[3]));
        atomicMax(&g_hmax[0], __float_as_uint(m));
    }
}

// ================= aggregation: warp per node, uint4 gathers =================

__global__ void __launch_bounds__(256)
agg_kernel(int insel, int n) {
    int w = (blockIdx.x * blockDim.x + threadIdx.x) >> 5;
    if (w >= n) return;
    int lane = threadIdx.x & 31;
    int c = lane & 15;
    int p = lane >> 4;
    const uint4* __restrict__ h4 =
        reinterpret_cast<const uint4*>(g_hb16[insel]);

    float a[8];
#pragma unroll
    for (int k = 0; k < 8; k++) a[k] = 0.0f;

    if (p == 0) {
        uint4 v = h4[(size_t)w * 16 + c];
        acc_bf2(a[0], a[1], v.x);
        acc_bf2(a[2], a[3], v.y);
        acc_bf2(a[4], a[5], v.z);
        acc_bf2(a[6], a[7], v.w);
    }

    int beg = g_off[w], end = g_off[w + 1];
    int e = beg + p;
    for (; e + 6 < end; e += 8) {
        int r0 = g_srt[e];
        int r1 = g_srt[e + 2];
        int r2 = g_srt[e + 4];
        int r3 = g_srt[e + 6];
        uint4 v0 = h4[(size_t)r0 * 16 + c];
        uint4 v1 = h4[(size_t)r1 * 16 + c];
        uint4 v2 = h4[(size_t)r2 * 16 + c];
        uint4 v3 = h4[(size_t)r3 * 16 + c];
        acc_bf2(a[0], a[1], v0.x); acc_bf2(a[2], a[3], v0.y);
        acc_bf2(a[4], a[5], v0.z); acc_bf2(a[6], a[7], v0.w);
        acc_bf2(a[0], a[1], v1.x); acc_bf2(a[2], a[3], v1.y);
        acc_bf2(a[4], a[5], v1.z); acc_bf2(a[6], a[7], v1.w);
        acc_bf2(a[0], a[1], v2.x); acc_bf2(a[2], a[3], v2.y);
        acc_bf2(a[4], a[5], v2.z); acc_bf2(a[6], a[7], v2.w);
        acc_bf2(a[0], a[1], v3.x); acc_bf2(a[2], a[3], v3.y);
        acc_bf2(a[4], a[5], v3.z); acc_bf2(a[6], a[7], v3.w);
    }
    for (; e < end; e += 2) {
        int r0 = g_srt[e];
        uint4 v0 = h4[(size_t)r0 * 16 + c];
        acc_bf2(a[0], a[1], v0.x); acc_bf2(a[2], a[3], v0.y);
        acc_bf2(a[4], a[5], v0.z); acc_bf2(a[6], a[7], v0.w);
    }

#pragma unroll
    for (int k = 0; k < 8; k++)
        a[k] += __shfl_xor_sync(0xffffffffu, a[k], 16);

    if (p == 0) {
        uint4 o;
        o.x = pack_bf2(a[0], a[1]);
        o.y = pack_bf2(a[2], a[3]);
        o.z = pack_bf2(a[4], a[5]);
        o.w = pack_bf2(a[6], a[7]);
        reinterpret_cast<uint4*>(g_aggb16)[(size_t)w * 16 + c] = o;
    }
}

// ====== FP8 QMMA GEMM: h_out = relu([h|agg] @ [Vw;Aw]^T + bias) ======
// Exact power-of-2 scaling: A_h/2^e1, A_agg/2^(e1+6), W x64. Single sync.
// smem: A0 16K | A1 16K | B0 16K | B1 16K | bias | dot | ow

#define S_A0   0
#define S_A1   16384
#define S_B0   32768
#define S_B1   49152
#define S_BIAS 65536
#define S_DOT  66048
#define S_OW   67072
#define GEMM_SMEM 68096

__global__ void __launch_bounds__(256, 2)
gemm_mma_kernel(int insel, int outsel, int l, int n,
                const float* __restrict__ Vb, const float* __restrict__ Ab,
                const float* __restrict__ Rb, const float* __restrict__ Rw,
                const float* __restrict__ ow, const float* __restrict__ ob,
                float* __restrict__ out) {
    extern __shared__ char smem[];
    float* sbias = (float*)(smem + S_BIAS);
    float* sdot  = (float*)(smem + S_DOT);
    float* sow   = (float*)(smem + S_OW);
    const int tid = threadIdx.x;
    const int wid = tid >> 5, lane = tid & 31;
    const int bm = blockIdx.x * 128;
    const int wm = (wid & 1) * 64;
    const int wn = (wid >> 1) * 32;
    const uint32_t sbase = smem_u32(smem);

    // ---- per-layer exact power-of-2 scale from max|h| ----
    unsigned hb = g_hmax[l];
    int e1 = ((int)(hb >> 23)) - 134;   // exp-7
    if (e1 < 0) e1 = 0;
    const float inv1 = __uint_as_float((uint32_t)(127 - e1) << 23); // 2^-e1
    const float fin  = __uint_as_float((uint32_t)(127 + e1) << 23); // 2^+e1
    const float inv2 = inv1 * 0.015625f;                            // 2^-(e1+6)

    // ---- prefetch both fp8 weight tiles (16KB each) ----
    const uint8_t* __restrict__ Wf8 = g_Wf8 + (size_t)l * 32768;
#pragma unroll
    for (int t = 0; t < 8; t++) {
        int idx = tid + t * 256;           // 0..2047
        int phase = idx >> 10;
        int r2 = idx & 1023;
        int row = r2 >> 3, cc = r2 & 7;
        uint32_t so = (uint32_t)(row * 128 + ((cc ^ (row & 7)) << 4));
        cp16(sbase + S_B0 + phase * 16384 + so,
             Wf8 + phase * 16384 + row * 128 + cc * 16);
    }
    CP_COMMIT();

    // bias while loads are in flight
    if (tid < 128) {
        float b = Vb[l * DIMX + tid] + Ab[l * DIMX + tid] + Rb[l * DIMX + tid];
        const float* __restrict__ ro = g_ro_all[l];
        const float* __restrict__ rw = Rw + (size_t)l * DIMX * DIMX
                                          + (size_t)tid * DIMX;
#pragma unroll 8
        for (int k = 0; k < DIMX; k++) b += ro[k] * rw[k];
        sbias[tid] = b;
    }
    if (l == 2) {
        sdot[tid] = 0.0f;
        sow[tid] = ow[tid];
    }

    // ---- convert A operands bf16 -> e4m3 into swizzled smem tiles ----
    auto convA = [&](const __nv_bfloat16* __restrict__ Asrc, int soff,
                     float inv) {
#pragma unroll
        for (int t = 0; t < 8; t++) {
            int idx = tid + t * 256;       // 0..2047
            int row = idx >> 4, q = idx & 15;
            int gm = bm + row;
            uint4 v = make_uint4(0, 0, 0, 0);
            if (gm < n)
                v = *(const uint4*)(Asrc + (size_t)gm * DIMX + q * 8);
            float f0 = __uint_as_float(v.x << 16) * inv;
            float f1 = __uint_as_float(v.x & 0xffff0000u) * inv;
            float f2 = __uint_as_float(v.y << 16) * inv;
            float f3 = __uint_as_float(v.y & 0xffff0000u) * inv;
            float f4 = __uint_as_float(v.z << 16) * inv;
            float f5 = __uint_as_float(v.z & 0xffff0000u) * inv;
            float f6 = __uint_as_float(v.w << 16) * inv;
            float f7 = __uint_as_float(v.w & 0xffff0000u) * inv;
            uint32_t w0 = pack_f8x4(f0, f1, f2, f3);
            uint32_t w1 = pack_f8x4(f4, f5, f6, f7);
            uint32_t off = (uint32_t)(row * 128 + (((q >> 1) ^ (row & 7)) << 4)
                                      + (q & 1) * 8);
            *(uint2*)(smem + soff + off) = make_uint2(w0, w1);
        }
    };
    convA(g_hb16[insel], S_A0, inv1);
    convA(g_aggb16, S_A1, inv2);

    float acc[4][4][4];
#pragma unroll
    for (int a = 0; a < 4; a++)
#pragma unroll
        for (int b = 0; b < 4; b++)
#pragma unroll
            for (int c = 0; c < 4; c++) acc[a][b][c] = 0.0f;

    auto compute = [&](int aoff, int boff) {
        const uint32_t sA = sbase + aoff;
        const uint32_t sB = sbase + boff;
#pragma unroll
        for (int ks = 0; ks < 4; ks++) {       // k32 fp8 per step, K=128/chunk
            const int kc = ks * 2;
            uint32_t a[4][4], b[2][4];
#pragma unroll
            for (int mi = 0; mi < 4; mi++) {
                int row = wm + mi * 16 + (lane & 15);
                int c = kc + (lane >> 4);
                ldm_x4(a[mi], sA + row * 128 + ((c ^ (row & 7)) << 4));
            }
#pragma unroll
            for (int nj = 0; nj < 2; nj++) {
                int row = wn + nj * 16 + ((lane >> 4) << 3) + (lane & 7);
                int c = kc + ((lane >> 3) & 1);
                ldm_x4(b[nj], sB + row * 128 + ((c ^ (row & 7)) << 4));
            }
#pragma unroll
            for (int mi = 0; mi < 4; mi++) {
                mma_fp8(acc[mi][0], a[mi], &b[0][0]);
                mma_fp8(acc[mi][1], a[mi], &b[0][2]);
                mma_fp8(acc[mi][2], a[mi], &b[1][0]);
                mma_fp8(acc[mi][3], a[mi], &b[1][2]);
            }
        }
    };

    CP_WAIT(0);
    __syncthreads();               // single sync: all tiles + bias visible
    compute(S_A0, S_B0);
#pragma unroll
    for (int a = 0; a < 4; a++)    // rescale: phase1 scale is 64x smaller
#pragma unroll
        for (int b = 0; b < 4; b++)
#pragma unroll
            for (int c = 0; c < 4; c++) acc[a][b][c] *= 0.015625f;
    compute(S_A1, S_B1);

    // ---- epilogue (result = acc * 2^e1 + bias) ----
    const int qr = lane >> 2;
    const int qc = (lane & 3) * 2;

    if (l < 2) {
        __nv_bfloat16* __restrict__ O = g_hb16[outsel];
        float* __restrict__ ro_next = g_ro_all[l + 1];
        float colsum[4][2];
        float vmax = 0.0f;
#pragma unroll
        for (int ni = 0; ni < 4; ni++) colsum[ni][0] = colsum[ni][1] = 0.0f;
#pragma unroll
        for (int mi = 0; mi < 4; mi++) {
            int r0 = bm + wm + mi * 16 + qr;
#pragma unroll
            for (int ni = 0; ni < 4; ni++) {
                int col = wn + ni * 8 + qc;
                float b0 = sbias[col], b1 = sbias[col + 1];
                float v0 = fmaxf(fmaf(acc[mi][ni][0], fin, b0), 0.f);
                float v1 = fmaxf(fmaf(acc[mi][ni][1], fin, b1), 0.f);
                float v2 = fmaxf(fmaf(acc[mi][ni][2], fin, b0), 0.f);
                float v3 = fmaxf(fmaf(acc[mi][ni][3], fin, b1), 0.f);
                if (r0 < n) {
                    *(uint32_t*)(O + (size_t)r0 * DIMX + col) = pack_bf2(v0, v1);
                    colsum[ni][0] += v0; colsum[ni][1] += v1;
                    vmax = fmaxf(vmax, fmaxf(v0, v1));
                }
                if (r0 + 8 < n) {
                    *(uint32_t*)(O + (size_t)(r0 + 8) * DIMX + col) =
                        pack_bf2(v2, v3);
                    colsum[ni][0] += v2; colsum[ni][1] += v3;
                    vmax = fmaxf(vmax, fmaxf(v2, v3));
                }
            }
        }
#pragma unroll
        for (int ni = 0; ni < 4; ni++)
#pragma unroll
            for (int j = 0; j < 2; j++) {
                float v = colsum[ni][j];
                v += __shfl_xor_sync(0xffffffffu, v, 4);
                v += __shfl_xor_sync(0xffffffffu, v, 8);
                v += __shfl_xor_sync(0xffffffffu, v, 16);
                if (lane < 4)
                    atomicAdd(&ro_next[wn + ni * 8 + lane * 2 + j], v);
            }
#pragma unroll
        for (int o = 16; o; o >>= 1)
            vmax = fmaxf(vmax, __shfl_xor_sync(0xffffffffu, vmax, o));
        if (lane == 0)
            atomicMax(&g_hmax[l + 1], __float_as_uint(vmax));
    } else {
        // final layer: sigmoid head fused; no h store, no readout
#pragma unroll
        for (int mi = 0; mi < 4; mi++) {
            int rl = wm + mi * 16 + qr;
            int r0 = bm + rl;
            float dA0 = 0.f, dA1 = 0.f, dB0 = 0.f, dB1 = 0.f;
#pragma unroll
            for (int ni = 0; ni < 4; ni++) {
                int col = wn + ni * 8 + qc;
                float b0 = sbias[col], b1 = sbias[col + 1];
                float w0 = sow[col], w1 = sow[col + 1];
                float u0 = sow[128 + col], u1 = sow[128 + col + 1];
                float v0 = fmaxf(fmaf(acc[mi][ni][0], fin, b0), 0.f);
                float v1 = fmaxf(fmaf(acc[mi][ni][1], fin, b1), 0.f);
                float v2 = fmaxf(fmaf(acc[mi][ni][2], fin, b0), 0.f);
                float v3 = fmaxf(fmaf(acc[mi][ni][3], fin, b1), 0.f);
                dA0 += v0 * w0 + v1 * w1;
                dA1 += v0 * u0 + v1 * u1;
                dB0 += v2 * w0 + v3 * w1;
                dB1 += v2 * u0 + v3 * u1;
            }
            if (r0 < n) {
                atomicAdd(&sdot[rl * 2 + 0], dA0);
                atomicAdd(&sdot[rl * 2 + 1], dA1);
            }
            if (r0 + 8 < n) {
                atomicAdd(&sdot[(rl + 8) * 2 + 0], dB0);
                atomicAdd(&sdot[(rl + 8) * 2 + 1], dB1);
            }
        }
        __syncthreads();
        if (tid < 128) {
            int gm = bm + tid;
            if (gm < n) {
                float z0 = sdot[tid * 2 + 0] + ob[0];
                float z1 = sdot[tid * 2 + 1] + ob[1];
                float2 o;
                o.x = 1.0f / (1.0f + __expf(-z0));
                o.y = 1.0f / (1.0f + __expf(-z1));
                *(float2*)(out + (size_t)gm * 2) = o;
            }
        }
    }
}

// ================= launch =================

extern "C" void kernel_launch(void* const* d_in, const int* in_sizes, int n_in,
                              void* d_out, int out_size) {
    const float* x  = (const float*)d_in[0];
    const int* src  = (const int*)d_in[1];
    const int* dst  = (const int*)d_in[2];
    const float* Vw = (const float*)d_in[3];
    const float* Vb = (const float*)d_in[4];
    const float* Aw = (const float*)d_in[5];
    const float* Ab = (const float*)d_in[6];
    const float* Rw = (const float*)d_in[7];
    const float* Rb = (const float*)d_in[8];
    const float* ow = (const float*)d_in[9];
    const float* ob = (const float*)d_in[10];
    float* out = (float*)d_out;

    const int n = in_sizes[0] / DIMX;   // 50000
    const int e = in_sizes[1];          // 800000

    cudaFuncSetAttribute(gemm_mma_kernel,
                         cudaFuncAttributeMaxDynamicSharedMemorySize, GEMM_SMEM);

    int n2 = (n * DIMX) / 2;
    setup_kernel<<<(n2 + 255) / 256, 256>>>(x, Vw, Aw, dst, n2, n, e);

    int nb = (n + 1023) / 1024;
    scan1_kernel<<<nb, 1024>>>(n);
    scan3_kernel<<<nb, 1024>>>(n);
    scatter_kernel<<<(e + 255) / 256, 256>>>(src, dst, e);
    readout0_kernel<<<512, 128>>>(n);

    for (int l = 0; l < 3; l++) {
        int insel = l & 1;       // 0,1,0
        int outsel = insel ^ 1;  // 1,0,1
        agg_kernel<<<(n * 32 + 255) / 256, 256>>>(insel, n);
        gemm_mma_kernel<<<(n + 127) / 128, 256, GEMM_SMEM>>>(
            insel, outsel, l, n, Vb, Ab, Rb, Rw, ow, ob, out);
    }
}

// round 12
// speedup vs baseline: 1.0563x; 1.0563x over previous
#include <cuda_runtime.h>
#include <cuda_bf16.h>
#include <cuda_fp16.h>
#include <cstdint>

#define NN 50000
#define DIMX 128
#define NE 800000

// ---- scratch (static __device__ globals; zero-initialized at load) ----
__device__ uint8_t g_h8[2][NN * DIMX];     // ping-pong hidden states, e4m3 (h/S_l)
__device__ uint8_t g_agg8[NN * DIMX];      // aggregation, e4m3 (agg/(64*S_l))
__device__ uint8_t g_Wf8[3 * 2 * DIMX * DIMX];  // weights e4m3, pre-scaled x64
__device__ int   g_off[NN + 1];
__device__ int   g_cnt[NN];     // degree counters; invariant: zero at launch entry
__device__ int   g_srt[NE];
__device__ int   g_bsum[64];
__device__ float g_ro_all[4][DIMX];   // readout per layer (true units)
__device__ float g_scale[4];          // S_l (power of 2); S_0 = 1

// ================= helpers =================

__device__ __forceinline__ uint32_t smem_u32(const void* p) {
    uint32_t a;
    asm("{ .reg .u64 t; cvta.to.shared.u64 t, %1; cvt.u32.u64 %0, t; }"
        : "=r"(a) : "l"(p));
    return a;
}

__device__ __forceinline__ void ldm_x4(uint32_t* r, uint32_t addr) {
    asm volatile("ldmatrix.sync.aligned.m8n8.x4.shared.b16 {%0,%1,%2,%3}, [%4];"
                 : "=r"(r[0]), "=r"(r[1]), "=r"(r[2]), "=r"(r[3]) : "r"(addr));
}

__device__ __forceinline__ void mma_fp8(float* c, const uint32_t* a,
                                        const uint32_t* b) {
    asm volatile(
        "mma.sync.aligned.m16n8k32.row.col.f32.e4m3.e4m3.f32 "
        "{%0,%1,%2,%3}, {%4,%5,%6,%7}, {%8,%9}, {%0,%1,%2,%3};"
        : "+f"(c[0]), "+f"(c[1]), "+f"(c[2]), "+f"(c[3])
        : "r"(a[0]), "r"(a[1]), "r"(a[2]), "r"(a[3]), "r"(b[0]), "r"(b[1]));
}

__device__ __forceinline__ void cp16(uint32_t dst, const void* src) {
    asm volatile("cp.async.cg.shared.global [%0], [%1], 16;"
                 :: "r"(dst), "l"(src) : "memory");
}
__device__ __forceinline__ void cp16z(uint32_t dst, const void* src, int sz) {
    asm volatile("cp.async.cg.shared.global [%0], [%1], 16, %2;"
                 :: "r"(dst), "l"(src), "r"(sz) : "memory");
}
#define CP_COMMIT() asm volatile("cp.async.commit_group;" ::: "memory")
#define CP_WAIT(N)  asm volatile("cp.async.wait_group %0;" :: "n"(N) : "memory")

// pack two f32 into one e4m3x2 halfword (byte0 = lo)
__device__ __forceinline__ uint16_t pack_f8x2(float lo, float hi) {
    uint16_t r;
    asm("cvt.rn.satfinite.e4m3x2.f32 %0, %1, %2;" : "=h"(r) : "f"(hi), "f"(lo));
    return r;
}

// 2 e4m3 (in low 16 bits) -> half2
__device__ __forceinline__ __half2 f8x2_to_h2(uint16_t w) {
    uint32_t r;
    asm("cvt.rn.f16x2.e4m3x2 %0, %1;" : "=r"(r) : "h"(w));
    return *reinterpret_cast<__half2*>(&r);
}

// half2 -> e4m3x2 halfword
__device__ __forceinline__ uint16_t h2_to_f8x2(__half2 h) {
    uint16_t r;
    asm("cvt.rn.satfinite.e4m3x2.f16x2 %0, %1;"
        : "=h"(r) : "r"(*reinterpret_cast<uint32_t*>(&h)));
    return r;
}

// accumulate 4 e4m3 packed in u32 into two half2 accumulators
__device__ __forceinline__ void acc_f8x4(__half2& a0, __half2& a1, uint32_t w) {
    a0 = __hadd2(a0, f8x2_to_h2((uint16_t)(w & 0xffffu)));
    a1 = __hadd2(a1, f8x2_to_h2((uint16_t)(w >> 16)));
}

// ====== setup: x->fp8 + W->fp8 + hist + zero ro + scale + g_off[n] ======

__global__ void setup_kernel(const float* __restrict__ x,
                             const float* __restrict__ Vw,
                             const float* __restrict__ Aw,
                             const int* __restrict__ dst,
                             int n2, int n, int e) {
    int i = blockIdx.x * blockDim.x + threadIdx.x;
    if (i < n2) {   // n2 = n*128/2 pairs; S_0 = 1
        float2 v = reinterpret_cast<const float2*>(x)[i];
        reinterpret_cast<uint16_t*>(g_h8[0])[i] = pack_f8x2(v.x, v.y);
    }
    if (i < 3 * 16384) {   // weight pairs, x64
        int el2 = i * 2;
        int l = el2 >> 15;
        int rem = el2 & 32767;
        int phase = rem >> 14;
        int el = rem & 16383;
        const float* W = phase ? Aw : Vw;
        float a = W[l * 16384 + el] * 64.0f;
        float b = W[l * 16384 + el + 1] * 64.0f;
        reinterpret_cast<uint16_t*>(g_Wf8)[i] = pack_f8x2(a, b);
    }
    if (i < e) atomicAdd(&g_cnt[dst[i]], 1);   // g_cnt zero on entry (invariant)
    if (i < 4 * DIMX) ((float*)g_ro_all)[i] = 0.0f;
    if (i == 0) { g_off[n] = e; g_scale[0] = 1.0f; }
}

// ================= CSR build =================

__global__ void scan1_kernel(int n) {
    __shared__ int s[1024];
    int i = blockIdx.x * 1024 + threadIdx.x;
    int v = (i < n) ? g_cnt[i] : 0;
    s[threadIdx.x] = v;
    __syncthreads();
    for (int off = 1; off < 1024; off <<= 1) {
        int t = (threadIdx.x >= off) ? s[threadIdx.x - off] : 0;
        __syncthreads();
        s[threadIdx.x] += t;
        __syncthreads();
    }
    if (i < n) g_off[i] = s[threadIdx.x] - v;
    if (threadIdx.x == 1023) g_bsum[blockIdx.x] = s[1023];
}

__global__ void scan3_kernel(int n) {
    __shared__ int spre[2];
    int tid = threadIdx.x;
    if (tid < 64) {
        int v = (tid < blockIdx.x) ? g_bsum[tid] : 0;
#pragma unroll
        for (int o = 16; o; o >>= 1) v += __shfl_xor_sync(0xffffffffu, v, o);
        if ((tid & 31) == 0) spre[tid >> 5] = v;
    }
    __syncthreads();
    int pre = spre[0] + spre[1];
    int i = blockIdx.x * 1024 + tid;
    if (i < n) g_off[i] += pre;
}

__global__ void scatter_kernel(const int* __restrict__ src,
                               const int* __restrict__ dst, int e) {
    int i = blockIdx.x * blockDim.x + threadIdx.x;
    if (i < e) {
        int d = dst[i];
        int pos = g_off[d] + atomicAdd(&g_cnt[d], -1) - 1;
        g_srt[pos] = src[i];
    }
}

// ============ readout of layer-0 input (fp8, S_0=1) ============

__global__ void readout0_kernel(int n) {
    const uint8_t* __restrict__ h = g_h8[0];
    int j = threadIdx.x;  // 64 threads, 2 cols each
    float s0 = 0.0f, s1 = 0.0f;
    for (int i = blockIdx.x; i < n; i += gridDim.x) {
        uint16_t w = *(const uint16_t*)(h + (size_t)i * DIMX + j * 2);
        __half2 v = f8x2_to_h2(w);
        s0 += __low2float(v);
        s1 += __high2float(v);
    }
    atomicAdd(&g_ro_all[0][j * 2 + 0], s0);
    atomicAdd(&g_ro_all[0][j * 2 + 1], s1);
}

// ========== aggregation: warp per node, fp8 rows (128B), half2 accumulate ====
// agg8[i] = (h8[i] + sum_{e} h8[srt[e]]) / 64

__global__ void __launch_bounds__(256)
agg_kernel(int insel, int n) {
    int w = (blockIdx.x * blockDim.x + threadIdx.x) >> 5;
    if (w >= n) return;
    int lane = threadIdx.x & 31;
    int c = lane & 7;    // 16B chunk within 128B row
    int p = lane >> 3;   // edge parity 0..3
    const uint4* __restrict__ h4 =
        reinterpret_cast<const uint4*>(g_h8[insel]);

    __half2 a[8];
#pragma unroll
    for (int k = 0; k < 8; k++) a[k] = __half2half2(__ushort_as_half(0));

    if (p == 0) {   // self row counted once
        uint4 v = h4[(size_t)w * 8 + c];
        acc_f8x4(a[0], a[1], v.x);
        acc_f8x4(a[2], a[3], v.y);
        acc_f8x4(a[4], a[5], v.z);
        acc_f8x4(a[6], a[7], v.w);
    }

    int beg = g_off[w], end = g_off[w + 1];
    int e = beg + p;
    for (; e + 12 < end; e += 16) {
        int r0 = g_srt[e];
        int r1 = g_srt[e + 4];
        int r2 = g_srt[e + 8];
        int r3 = g_srt[e + 12];
        uint4 v0 = h4[(size_t)r0 * 8 + c];
        uint4 v1 = h4[(size_t)r1 * 8 + c];
        uint4 v2 = h4[(size_t)r2 * 8 + c];
        uint4 v3 = h4[(size_t)r3 * 8 + c];
        acc_f8x4(a[0], a[1], v0.x); acc_f8x4(a[2], a[3], v0.y);
        acc_f8x4(a[4], a[5], v0.z); acc_f8x4(a[6], a[7], v0.w);
        acc_f8x4(a[0], a[1], v1.x); acc_f8x4(a[2], a[3], v1.y);
        acc_f8x4(a[4], a[5], v1.z); acc_f8x4(a[6], a[7], v1.w);
        acc_f8x4(a[0], a[1], v2.x); acc_f8x4(a[2], a[3], v2.y);
        acc_f8x4(a[4], a[5], v2.z); acc_f8x4(a[6], a[7], v2.w);
        acc_f8x4(a[0], a[1], v3.x); acc_f8x4(a[2], a[3], v3.y);
        acc_f8x4(a[4], a[5], v3.z); acc_f8x4(a[6], a[7], v3.w);
    }
    for (; e < end; e += 4) {
        int r0 = g_srt[e];
        uint4 v0 = h4[(size_t)r0 * 8 + c];
        acc_f8x4(a[0], a[1], v0.x); acc_f8x4(a[2], a[3], v0.y);
        acc_f8x4(a[4], a[5], v0.z); acc_f8x4(a[6], a[7], v0.w);
    }

    // combine 4 parity groups (lane bits 3,4)
#pragma unroll
    for (int k = 0; k < 8; k++) {
        uint32_t u = *reinterpret_cast<uint32_t*>(&a[k]);
        uint32_t u1 = __shfl_xor_sync(0xffffffffu, u, 8);
        a[k] = __hadd2(a[k], *reinterpret_cast<__half2*>(&u1));
        u = *reinterpret_cast<uint32_t*>(&a[k]);
        uint32_t u2 = __shfl_xor_sync(0xffffffffu, u, 16);
        a[k] = __hadd2(a[k], *reinterpret_cast<__half2*>(&u2));
    }

    if (p == 0) {
        const __half2 s64 = __float2half2_rn(0.015625f);   // exact 1/64
        uint16_t q[8];
#pragma unroll
        for (int k = 0; k < 8; k++) q[k] = h2_to_f8x2(__hmul2(a[k], s64));
        uint4 o;
        o.x = (uint32_t)q[0] | ((uint32_t)q[1] << 16);
        o.y = (uint32_t)q[2] | ((uint32_t)q[3] << 16);
        o.z = (uint32_t)q[4] | ((uint32_t)q[5] << 16);
        o.w = (uint32_t)q[6] | ((uint32_t)q[7] << 16);
        reinterpret_cast<uint4*>(g_agg8)[(size_t)w * 8 + c] = o;
    }
}

// ====== FP8 QMMA GEMM, all-fp8 operands direct cp.async; bias fused; head l==2
// h_out = relu([h|agg] @ [Vw;Aw]^T + bias); scale chain via g_scale.
// smem: A0 16K | A1 16K | B0 16K | B1 16K | bias | dot | ow | spart

#define S_A0   0
#define S_A1   16384
#define S_B0   32768
#define S_B1   49152
#define S_BIAS 65536
#define S_DOT  66048
#define S_OW   67072
#define S_SP   68096
#define GEMM_SMEM 68608

__global__ void __launch_bounds__(256, 2)
gemm_mma_kernel(int insel, int outsel, int l, int n,
                const float* __restrict__ Vb, const float* __restrict__ Ab,
                const float* __restrict__ Rb, const float* __restrict__ Rw,
                const float* __restrict__ ow, const float* __restrict__ ob,
                float* __restrict__ out) {
    extern __shared__ char smem[];
    float* sbias = (float*)(smem + S_BIAS);
    float* sdot  = (float*)(smem + S_DOT);
    float* sow   = (float*)(smem + S_OW);
    float* spart = (float*)(smem + S_SP);
    const int tid = threadIdx.x;
    const int wid = tid >> 5, lane = tid & 31;
    const int bm = blockIdx.x * 128;
    const int wm = (wid & 1) * 64;
    const int wn = (wid >> 1) * 32;
    const uint32_t sbase = smem_u32(smem);

    const float fin = g_scale[l];   // S_in (power of 2)

    // ---- prefetch all 4 fp8 tiles (16KB each) ----
    const uint8_t* __restrict__ A0 = g_h8[insel];
    const uint8_t* __restrict__ A1 = g_agg8;
    const uint8_t* __restrict__ Wf8 = g_Wf8 + (size_t)l * 32768;
#pragma unroll
    for (int t = 0; t < 4; t++) {
        int idx = tid + t * 256;       // 0..1023 per tile
        int row = idx >> 3, cc = idx & 7;
        uint32_t so = (uint32_t)(row * 128 + ((cc ^ (row & 7)) << 4));
        int gm = bm + row;
        int gmc = gm < n ? gm : 0;
        int sz = gm < n ? 16 : 0;
        cp16z(sbase + S_A0 + so, A0 + (size_t)gmc * DIMX + cc * 16, sz);
        cp16z(sbase + S_A1 + so, A1 + (size_t)gmc * DIMX + cc * 16, sz);
        cp16(sbase + S_B0 + so, Wf8 + row * 128 + cc * 16);
        cp16(sbase + S_B1 + so, Wf8 + 16384 + row * 128 + cc * 16);
    }
    CP_COMMIT();

    // bias while loads are in flight; per-warp |bias| max partials
    if (tid < 128) {
        float b = Vb[l * DIMX + tid] + Ab[l * DIMX + tid] + Rb[l * DIMX + tid];
        const float* __restrict__ ro = g_ro_all[l];
        const float* __restrict__ rw = Rw + (size_t)l * DIMX * DIMX
                                          + (size_t)tid * DIMX;
#pragma unroll 8
        for (int k = 0; k < DIMX; k++) b += ro[k] * rw[k];
        sbias[tid] = b;
        float m = fabsf(b);
#pragma unroll
        for (int o = 16; o; o >>= 1)
            m = fmaxf(m, __shfl_xor_sync(0xffffffffu, m, o));
        if (lane == 0) spart[wid] = m;
    }
    if (l == 2) {
        sdot[tid] = 0.0f;
        sow[tid] = ow[tid];
    }

    float acc[4][4][4];
#pragma unroll
    for (int a = 0; a < 4; a++)
#pragma unroll
        for (int b = 0; b < 4; b++)
#pragma unroll
            for (int c = 0; c < 4; c++) acc[a][b][c] = 0.0f;

    auto compute = [&](int aoff, int boff) {
        const uint32_t sA = sbase + aoff;
        const uint32_t sB = sbase + boff;
#pragma unroll
        for (int ks = 0; ks < 4; ks++) {       // K=32 fp8 per step
            const int kc = ks * 2;
            uint32_t a[4][4], b[2][4];
#pragma unroll
            for (int mi = 0; mi < 4; mi++) {
                int row = wm + mi * 16 + (lane & 15);
                int c = kc + (lane >> 4);
                ldm_x4(a[mi], sA + row * 128 + ((c ^ (row & 7)) << 4));
            }
#pragma unroll
            for (int nj = 0; nj < 2; nj++) {
                int row = wn + nj * 16 + ((lane >> 4) << 3) + (lane & 7);
                int c = kc + ((lane >> 3) & 1);
                ldm_x4(b[nj], sB + row * 128 + ((c ^ (row & 7)) << 4));
            }
#pragma unroll
            for (int mi = 0; mi < 4; mi++) {
                mma_fp8(acc[mi][0], a[mi], &b[0][0]);
                mma_fp8(acc[mi][1], a[mi], &b[0][2]);
                mma_fp8(acc[mi][2], a[mi], &b[1][0]);
                mma_fp8(acc[mi][3], a[mi], &b[1][2]);
            }
        }
    };

    CP_WAIT(0);
    __syncthreads();   // tiles + bias + spart + sdot visible

    // uniform output scale S_out = 2^(exp(max|bias|)+4)  (>=8x headroom)
    float mb = fmaxf(fmaxf(spart[0], spart[1]), fmaxf(spart[2], spart[3]));
    int eo = ((int)((__float_as_uint(mb) >> 23) & 0xff)) - 127 + 4;
    if (eo < -60) eo = -60;
    if (eo > 60) eo = 60;
    const float inv_out = __uint_as_float((uint32_t)(127 - eo) << 23);
    const float S_out   = __uint_as_float((uint32_t)(127 + eo) << 23);
    if (tid == 0 && l < 2) g_scale[l + 1] = S_out;

    compute(S_A0, S_B0);
#pragma unroll
    for (int a = 0; a < 4; a++)    // phase-0 operands are 64x larger
#pragma unroll
        for (int b = 0; b < 4; b++)
#pragma unroll
            for (int c = 0; c < 4; c++) acc[a][b][c] *= 0.015625f;
    compute(S_A1, S_B1);

    // ---- epilogue (true value = acc * S_in + bias) ----
    const int qr = lane >> 2;
    const int qc = (lane & 3) * 2;

    if (l < 2) {
        uint8_t* __restrict__ O = g_h8[outsel];
        float* __restrict__ ro_next = g_ro_all[l + 1];
        float colsum[4][2];
#pragma unroll
        for (int ni = 0; ni < 4; ni++) colsum[ni][0] = colsum[ni][1] = 0.0f;
#pragma unroll
        for (int mi = 0; mi < 4; mi++) {
            int r0 = bm + wm + mi * 16 + qr;
#pragma unroll
            for (int ni = 0; ni < 4; ni++) {
                int col = wn + ni * 8 + qc;
                float b0 = sbias[col], b1 = sbias[col + 1];
                float v0 = fmaxf(fmaf(acc[mi][ni][0], fin, b0), 0.f);
                float v1 = fmaxf(fmaf(acc[mi][ni][1], fin, b1), 0.f);
                float v2 = fmaxf(fmaf(acc[mi][ni][2], fin, b0), 0.f);
                float v3 = fmaxf(fmaf(acc[mi][ni][3], fin, b1), 0.f);
                if (r0 < n) {
                    *(uint16_t*)(O + (size_t)r0 * DIMX + col) =
                        pack_f8x2(v0 * inv_out, v1 * inv_out);
                    colsum[ni][0] += v0; colsum[ni][1] += v1;
                }
                if (r0 + 8 < n) {
                    *(uint16_t*)(O + (size_t)(r0 + 8) * DIMX + col) =
                        pack_f8x2(v2 * inv_out, v3 * inv_out);
                    colsum[ni][0] += v2; colsum[ni][1] += v3;
                }
            }
        }
#pragma unroll
        for (int ni = 0; ni < 4; ni++)
#pragma unroll
            for (int j = 0; j < 2; j++) {
                float v = colsum[ni][j];
                v += __shfl_xor_sync(0xffffffffu, v, 4);
                v += __shfl_xor_sync(0xffffffffu, v, 8);
                v += __shfl_xor_sync(0xffffffffu, v, 16);
                if (lane < 4)
                    atomicAdd(&ro_next[wn + ni * 8 + lane * 2 + j], v);
            }
    } else {
        // final layer: sigmoid head fused; no h store, no readout
#pragma unroll
        for (int mi = 0; mi < 4; mi++) {
            int rl = wm + mi * 16 + qr;
            int r0 = bm + rl;
            float dA0 = 0.f, dA1 = 0.f, dB0 = 0.f, dB1 = 0.f;
#pragma unroll
            for (int ni = 0; ni < 4; ni++) {
                int col = wn + ni * 8 + qc;
                float b0 = sbias[col], b1 = sbias[col + 1];
                float w0 = sow[col], w1 = sow[col + 1];
                float u0 = sow[128 + col], u1 = sow[128 + col + 1];
                float v0 = fmaxf(fmaf(acc[mi][ni][0], fin, b0), 0.f);
                float v1 = fmaxf(fmaf(acc[mi][ni][1], fin, b1), 0.f);
                float v2 = fmaxf(fmaf(acc[mi][ni][2], fin, b0), 0.f);
                float v3 = fmaxf(fmaf(acc[mi][ni][3], fin, b1), 0.f);
                dA0 += v0 * w0 + v1 * w1;
                dA1 += v0 * u0 + v1 * u1;
                dB0 += v2 * w0 + v3 * w1;
                dB1 += v2 * u0 + v3 * u1;
            }
            if (r0 < n) {
                atomicAdd(&sdot[rl * 2 + 0], dA0);
                atomicAdd(&sdot[rl * 2 + 1], dA1);
            }
            if (r0 + 8 < n) {
                atomicAdd(&sdot[(rl + 8) * 2 + 0], dB0);
                atomicAdd(&sdot[(rl + 8) * 2 + 1], dB1);
            }
        }
        __syncthreads();
        if (tid < 128) {
            int gm = bm + tid;
            if (gm < n) {
                float z0 = sdot[tid * 2 + 0] + ob[0];
                float z1 = sdot[tid * 2 + 1] + ob[1];
                float2 o;
                o.x = 1.0f / (1.0f + __expf(-z0));
                o.y = 1.0f / (1.0f + __expf(-z1));
                *(float2*)(out + (size_t)gm * 2) = o;
            }
        }
    }
}

// ================= launch =================

extern "C" void kernel_launch(void* const* d_in, const int* in_sizes, int n_in,
                              void* d_out, int out_size) {
    const float* x  = (const float*)d_in[0];
    const int* src  = (const int*)d_in[1];
    const int* dst  = (const int*)d_in[2];
    const float* Vw = (const float*)d_in[3];
    const float* Vb = (const float*)d_in[4];
    const float* Aw = (const float*)d_in[5];
    const float* Ab = (const float*)d_in[6];
    const float* Rw = (const float*)d_in[7];
    const float* Rb = (const float*)d_in[8];
    const float* ow = (const float*)d_in[9];
    const float* ob = (const float*)d_in[10];
    float* out = (float*)d_out;

    const int n = in_sizes[0] / DIMX;   // 50000
    const int e = in_sizes[1];          // 800000

    cudaFuncSetAttribute(gemm_mma_kernel,
                         cudaFuncAttributeMaxDynamicSharedMemorySize, GEMM_SMEM);

    int n2 = (n * DIMX) / 2;
    setup_kernel<<<(n2 + 255) / 256, 256>>>(x, Vw, Aw, dst, n2, n, e);

    int nb = (n + 1023) / 1024;
    scan1_kernel<<<nb, 1024>>>(n);
    scan3_kernel<<<nb, 1024>>>(n);
    scatter_kernel<<<(e + 255) / 256, 256>>>(src, dst, e);
    readout0_kernel<<<512, 64>>>(n);

    for (int l = 0; l < 3; l++) {
        int insel = l & 1;       // 0,1,0
        int outsel = insel ^ 1;  // 1,0,1
        agg_kernel<<<(n * 32 + 255) / 256, 256>>>(insel, n);
        gemm_mma_kernel<<<(n + 127) / 128, 256, GEMM_SMEM>>>(
            insel, outsel, l, n, Vb, Ab, Rb, Rw, ow, ob, out);
    }
}

// round 13
// speedup vs baseline: 1.4779x; 1.3991x over previous
#include <cuda_runtime.h>
#include <cuda_bf16.h>
#include <cuda_fp16.h>
#include <cstdint>

#define NN 50000
#define DIMX 128
#define NE 800000

// ---- scratch (static __device__ globals; zero-initialized at load) ----
__device__ uint8_t g_h8[2][NN * DIMX];     // ping-pong hidden states, e4m3 (h/S_l)
__device__ uint8_t g_agg8[NN * DIMX];      // aggregation, e4m3 (agg/(64*S_l))
__device__ uint8_t g_Wf8[3 * 2 * DIMX * DIMX];  // weights e4m3, pre-scaled x64
__device__ int   g_off[NN + 1];
__device__ int   g_cnt[NN];     // degree counters; invariant: zero at launch entry
__device__ int   g_srt[NE];
__device__ int   g_bsum[64];
__device__ float g_ro_all[4][DIMX];   // readout per layer (true units)
__device__ float g_bias[DIMX];        // combined bias for current layer
__device__ float g_scale[4];          // S_l (power of 2); S_0 = 1
__device__ float g_iscale[4];         // 1/S_l

// ================= helpers =================

__device__ __forceinline__ uint32_t smem_u32(const void* p) {
    uint32_t a;
    asm("{ .reg .u64 t; cvta.to.shared.u64 t, %1; cvt.u32.u64 %0, t; }"
        : "=r"(a) : "l"(p));
    return a;
}

__device__ __forceinline__ void ldm_x4(uint32_t* r, uint32_t addr) {
    asm volatile("ldmatrix.sync.aligned.m8n8.x4.shared.b16 {%0,%1,%2,%3}, [%4];"
                 : "=r"(r[0]), "=r"(r[1]), "=r"(r[2]), "=r"(r[3]) : "r"(addr));
}

__device__ __forceinline__ void mma_fp8(float* c, const uint32_t* a,
                                        const uint32_t* b) {
    asm volatile(
        "mma.sync.aligned.m16n8k32.row.col.f32.e4m3.e4m3.f32 "
        "{%0,%1,%2,%3}, {%4,%5,%6,%7}, {%8,%9}, {%0,%1,%2,%3};"
        : "+f"(c[0]), "+f"(c[1]), "+f"(c[2]), "+f"(c[3])
        : "r"(a[0]), "r"(a[1]), "r"(a[2]), "r"(a[3]), "r"(b[0]), "r"(b[1]));
}

__device__ __forceinline__ void cp16(uint32_t dst, const void* src) {
    asm volatile("cp.async.cg.shared.global [%0], [%1], 16;"
                 :: "r"(dst), "l"(src) : "memory");
}
__device__ __forceinline__ void cp16z(uint32_t dst, const void* src, int sz) {
    asm volatile("cp.async.cg.shared.global [%0], [%1], 16, %2;"
                 :: "r"(dst), "l"(src), "r"(sz) : "memory");
}
#define CP_COMMIT() asm volatile("cp.async.commit_group;" ::: "memory")
#define CP_WAIT(N)  asm volatile("cp.async.wait_group %0;" :: "n"(N) : "memory")

// pack two f32 into one e4m3x2 halfword (byte0 = lo)
__device__ __forceinline__ uint16_t pack_f8x2(float lo, float hi) {
    uint16_t r;
    asm("cvt.rn.satfinite.e4m3x2.f32 %0, %1, %2;" : "=h"(r) : "f"(hi), "f"(lo));
    return r;
}

// 2 e4m3 (in low 16 bits) -> half2
__device__ __forceinline__ __half2 f8x2_to_h2(uint16_t w) {
    uint32_t r;
    asm("cvt.rn.f16x2.e4m3x2 %0, %1;" : "=r"(r) : "h"(w));
    return *reinterpret_cast<__half2*>(&r);
}

// half2 -> e4m3x2 halfword
__device__ __forceinline__ uint16_t h2_to_f8x2(__half2 h) {
    uint16_t r;
    asm("cvt.rn.satfinite.e4m3x2.f16x2 %0, %1;"
        : "=h"(r) : "r"(*reinterpret_cast<uint32_t*>(&h)));
    return r;
}

// accumulate 4 e4m3 packed in u32 into two half2 accumulators
__device__ __forceinline__ void acc_f8x4(__half2& a0, __half2& a1, uint32_t w) {
    a0 = __hadd2(a0, f8x2_to_h2((uint16_t)(w & 0xffffu)));
    a1 = __hadd2(a1, f8x2_to_h2((uint16_t)(w >> 16)));
}

// ====== setup: x->fp8 + W->fp8 + hist + zero ro + scale + g_off[n] ======

__global__ void setup_kernel(const float* __restrict__ x,
                             const float* __restrict__ Vw,
                             const float* __restrict__ Aw,
                             const int* __restrict__ dst,
                             int n2, int n, int e) {
    int i = blockIdx.x * blockDim.x + threadIdx.x;
    if (i < n2) {   // n2 = n*128/2 pairs; S_0 = 1
        float2 v = reinterpret_cast<const float2*>(x)[i];
        reinterpret_cast<uint16_t*>(g_h8[0])[i] = pack_f8x2(v.x, v.y);
    }
    if (i < 3 * 16384) {   // weight pairs, x64
        int el2 = i * 2;
        int l = el2 >> 15;
        int rem = el2 & 32767;
        int phase = rem >> 14;
        int el = rem & 16383;
        const float* W = phase ? Aw : Vw;
        float a = W[l * 16384 + el] * 64.0f;
        float b = W[l * 16384 + el + 1] * 64.0f;
        reinterpret_cast<uint16_t*>(g_Wf8)[i] = pack_f8x2(a, b);
    }
    if (i < e) atomicAdd(&g_cnt[dst[i]], 1);   // g_cnt zero on entry (invariant)
    if (i < 4 * DIMX) ((float*)g_ro_all)[i] = 0.0f;
    if (i == 0) { g_off[n] = e; g_scale[0] = 1.0f; g_iscale[0] = 1.0f; }
}

// ================= CSR build =================

__global__ void scan1_kernel(int n) {
    __shared__ int s[1024];
    int i = blockIdx.x * 1024 + threadIdx.x;
    int v = (i < n) ? g_cnt[i] : 0;
    s[threadIdx.x] = v;
    __syncthreads();
    for (int off = 1; off < 1024; off <<= 1) {
        int t = (threadIdx.x >= off) ? s[threadIdx.x - off] : 0;
        __syncthreads();
        s[threadIdx.x] += t;
        __syncthreads();
    }
    if (i < n) g_off[i] = s[threadIdx.x] - v;
    if (threadIdx.x == 1023) g_bsum[blockIdx.x] = s[1023];
}

__global__ void scan3_kernel(int n) {
    __shared__ int spre[2];
    int tid = threadIdx.x;
    if (tid < 64) {
        int v = (tid < blockIdx.x) ? g_bsum[tid] : 0;
#pragma unroll
        for (int o = 16; o; o >>= 1) v += __shfl_xor_sync(0xffffffffu, v, o);
        if ((tid & 31) == 0) spre[tid >> 5] = v;
    }
    __syncthreads();
    int pre = spre[0] + spre[1];
    int i = blockIdx.x * 1024 + tid;
    if (i < n) g_off[i] += pre;
}

__global__ void scatter_kernel(const int* __restrict__ src,
                               const int* __restrict__ dst, int e) {
    int i = blockIdx.x * blockDim.x + threadIdx.x;
    if (i < e) {
        int d = dst[i];
        int pos = g_off[d] + atomicAdd(&g_cnt[d], -1) - 1;
        g_srt[pos] = src[i];
    }
}

// ============ readout of layer-0 input (fp8, S_0=1) ============

__global__ void readout0_kernel(int n) {
    const uint8_t* __restrict__ h = g_h8[0];
    int j = threadIdx.x;  // 64 threads, 2 cols each
    float s0 = 0.0f, s1 = 0.0f;
    for (int i = blockIdx.x; i < n; i += gridDim.x) {
        uint16_t w = *(const uint16_t*)(h + (size_t)i * DIMX + j * 2);
        __half2 v = f8x2_to_h2(w);
        s0 += __low2float(v);
        s1 += __high2float(v);
    }
    atomicAdd(&g_ro_all[0][j * 2 + 0], s0);
    atomicAdd(&g_ro_all[0][j * 2 + 1], s1);
}

// ============ per-layer bias: b = Vb+Ab+Rb + ro@Rw^T; also output scale ======
// one block, 1024 threads; warp w owns outputs 4w..4w+3, coalesced Rw reads.

__global__ void bias_kernel(const float* __restrict__ Vb,
                            const float* __restrict__ Ab,
                            const float* __restrict__ Rb,
                            const float* __restrict__ Rw, int l) {
    __shared__ float smax[32];
    int tid = threadIdx.x;
    int wid = tid >> 5, lane = tid & 31;
    const float* __restrict__ ro = g_ro_all[l];
    float4 r4 = reinterpret_cast<const float4*>(ro)[lane];
    float mymax = 0.0f;
#pragma unroll
    for (int q = 0; q < 4; q++) {
        int j = wid * 4 + q;
        float4 w4 = reinterpret_cast<const float4*>(
            Rw + (size_t)l * 16384 + (size_t)j * DIMX)[lane];
        float s = w4.x * r4.x + w4.y * r4.y + w4.z * r4.z + w4.w * r4.w;
#pragma unroll
        for (int o = 16; o; o >>= 1)
            s += __shfl_xor_sync(0xffffffffu, s, o);
        if (lane == 0) {
            float b = s + Vb[l * DIMX + j] + Ab[l * DIMX + j] + Rb[l * DIMX + j];
            g_bias[j] = b;
            mymax = fmaxf(mymax, fabsf(b));
        }
    }
    if (lane == 0) smax[wid] = mymax;
    __syncthreads();
    if (tid == 0) {
        float m = 0.0f;
#pragma unroll
        for (int i = 0; i < 32; i++) m = fmaxf(m, smax[i]);
        int eo = ((int)((__float_as_uint(m) >> 23) & 0xff)) - 127 + 4;
        if (eo < -60) eo = -60;
        if (eo > 60) eo = 60;
        g_scale[l + 1]  = __uint_as_float((uint32_t)(127 + eo) << 23);
        g_iscale[l + 1] = __uint_as_float((uint32_t)(127 - eo) << 23);
    }
}

// ========== aggregation: warp per node, fp8 rows (128B), half2 accumulate ====
// agg8[i] = (h8[i] + sum_{e} h8[srt[e]]) / 64

__global__ void __launch_bounds__(256)
agg_kernel(int insel, int n) {
    int w = (blockIdx.x * blockDim.x + threadIdx.x) >> 5;
    if (w >= n) return;
    int lane = threadIdx.x & 31;
    int c = lane & 7;    // 16B chunk within 128B row
    int p = lane >> 3;   // edge parity 0..3
    const uint4* __restrict__ h4 =
        reinterpret_cast<const uint4*>(g_h8[insel]);

    __half2 a[8];
#pragma unroll
    for (int k = 0; k < 8; k++) a[k] = __half2half2(__ushort_as_half(0));

    if (p == 0) {   // self row counted once
        uint4 v = h4[(size_t)w * 8 + c];
        acc_f8x4(a[0], a[1], v.x);
        acc_f8x4(a[2], a[3], v.y);
        acc_f8x4(a[4], a[5], v.z);
        acc_f8x4(a[6], a[7], v.w);
    }

    int beg = g_off[w], end = g_off[w + 1];
    int e = beg + p;
    for (; e + 12 < end; e += 16) {
        int r0 = g_srt[e];
        int r1 = g_srt[e + 4];
        int r2 = g_srt[e + 8];
        int r3 = g_srt[e + 12];
        uint4 v0 = h4[(size_t)r0 * 8 + c];
        uint4 v1 = h4[(size_t)r1 * 8 + c];
        uint4 v2 = h4[(size_t)r2 * 8 + c];
        uint4 v3 = h4[(size_t)r3 * 8 + c];
        acc_f8x4(a[0], a[1], v0.x); acc_f8x4(a[2], a[3], v0.y);
        acc_f8x4(a[4], a[5], v0.z); acc_f8x4(a[6], a[7], v0.w);
        acc_f8x4(a[0], a[1], v1.x); acc_f8x4(a[2], a[3], v1.y);
        acc_f8x4(a[4], a[5], v1.z); acc_f8x4(a[6], a[7], v1.w);
        acc_f8x4(a[0], a[1], v2.x); acc_f8x4(a[2], a[3], v2.y);
        acc_f8x4(a[4], a[5], v2.z); acc_f8x4(a[6], a[7], v2.w);
        acc_f8x4(a[0], a[1], v3.x); acc_f8x4(a[2], a[3], v3.y);
        acc_f8x4(a[4], a[5], v3.z); acc_f8x4(a[6], a[7], v3.w);
    }
    for (; e < end; e += 4) {
        int r0 = g_srt[e];
        uint4 v0 = h4[(size_t)r0 * 8 + c];
        acc_f8x4(a[0], a[1], v0.x); acc_f8x4(a[2], a[3], v0.y);
        acc_f8x4(a[4], a[5], v0.z); acc_f8x4(a[6], a[7], v0.w);
    }

    // combine 4 parity groups (lane bits 3,4)
#pragma unroll
    for (int k = 0; k < 8; k++) {
        uint32_t u = *reinterpret_cast<uint32_t*>(&a[k]);
        uint32_t u1 = __shfl_xor_sync(0xffffffffu, u, 8);
        a[k] = __hadd2(a[k], *reinterpret_cast<__half2*>(&u1));
        u = *reinterpret_cast<uint32_t*>(&a[k]);
        uint32_t u2 = __shfl_xor_sync(0xffffffffu, u, 16);
        a[k] = __hadd2(a[k], *reinterpret_cast<__half2*>(&u2));
    }

    if (p == 0) {
        const __half2 s64 = __float2half2_rn(0.015625f);   // exact 1/64
        uint16_t q[8];
#pragma unroll
        for (int k = 0; k < 8; k++) q[k] = h2_to_f8x2(__hmul2(a[k], s64));
        uint4 o;
        o.x = (uint32_t)q[0] | ((uint32_t)q[1] << 16);
        o.y = (uint32_t)q[2] | ((uint32_t)q[3] << 16);
        o.z = (uint32_t)q[4] | ((uint32_t)q[5] << 16);
        o.w = (uint32_t)q[6] | ((uint32_t)q[7] << 16);
        reinterpret_cast<uint4*>(g_agg8)[(size_t)w * 8 + c] = o;
    }
}

// ====== FP8 QMMA GEMM, all-fp8 operands direct cp.async; bias precomputed ====
// h_out = relu([h|agg] @ [Vw;Aw]^T + bias); scale chain via g_scale/g_iscale.
// smem: A0 16K | A1 16K | B0 16K | B1 16K | bias | dot | ow

#define S_A0   0
#define S_A1   16384
#define S_B0   32768
#define S_B1   49152
#define S_BIAS 65536
#define S_DOT  66048
#define S_OW   67072
#define GEMM_SMEM 68096

__global__ void __launch_bounds__(256, 2)
gemm_mma_kernel(int insel, int outsel, int l, int n,
                const float* __restrict__ ow, const float* __restrict__ ob,
                float* __restrict__ out) {
    extern __shared__ char smem[];
    float* sbias = (float*)(smem + S_BIAS);
    float* sdot  = (float*)(smem + S_DOT);
    float* sow   = (float*)(smem + S_OW);
    const int tid = threadIdx.x;
    const int wid = tid >> 5, lane = tid & 31;
    const int bm = blockIdx.x * 128;
    const int wm = (wid & 1) * 64;
    const int wn = (wid >> 1) * 32;
    const uint32_t sbase = smem_u32(smem);

    const float fin = g_scale[l];                       // S_in (power of 2)
    const float inv_out = (l < 2) ? g_iscale[l + 1] : 1.0f;

    // ---- prefetch all 4 fp8 tiles (16KB each) ----
    const uint8_t* __restrict__ A0 = g_h8[insel];
    const uint8_t* __restrict__ A1 = g_agg8;
    const uint8_t* __restrict__ Wf8 = g_Wf8 + (size_t)l * 32768;
#pragma unroll
    for (int t = 0; t < 4; t++) {
        int idx = tid + t * 256;       // 0..1023 per tile
        int row = idx >> 3, cc = idx & 7;
        uint32_t so = (uint32_t)(row * 128 + ((cc ^ (row & 7)) << 4));
        int gm = bm + row;
        int gmc = gm < n ? gm : 0;
        int sz = gm < n ? 16 : 0;
        cp16z(sbase + S_A0 + so, A0 + (size_t)gmc * DIMX + cc * 16, sz);
        cp16z(sbase + S_A1 + so, A1 + (size_t)gmc * DIMX + cc * 16, sz);
        cp16(sbase + S_B0 + so, Wf8 + row * 128 + cc * 16);
        cp16(sbase + S_B1 + so, Wf8 + 16384 + row * 128 + cc * 16);
    }
    CP_COMMIT();

    // bias: precomputed per layer, one coalesced load
    if (tid < 128) sbias[tid] = g_bias[tid];
    if (l == 2) {
        sdot[tid] = 0.0f;
        sow[tid] = ow[tid];
    }

    float acc[4][4][4];
#pragma unroll
    for (int a = 0; a < 4; a++)
#pragma unroll
        for (int b = 0; b < 4; b++)
#pragma unroll
            for (int c = 0; c < 4; c++) acc[a][b][c] = 0.0f;

    auto compute = [&](int aoff, int boff) {
        const uint32_t sA = sbase + aoff;
        const uint32_t sB = sbase + boff;
#pragma unroll
        for (int ks = 0; ks < 4; ks++) {       // K=32 fp8 per step
            const int kc = ks * 2;
            uint32_t a[4][4], b[2][4];
#pragma unroll
            for (int mi = 0; mi < 4; mi++) {
                int row = wm + mi * 16 + (lane & 15);
                int c = kc + (lane >> 4);
                ldm_x4(a[mi], sA + row * 128 + ((c ^ (row & 7)) << 4));
            }
#pragma unroll
            for (int nj = 0; nj < 2; nj++) {
                int row = wn + nj * 16 + ((lane >> 4) << 3) + (lane & 7);
                int c = kc + ((lane >> 3) & 1);
                ldm_x4(b[nj], sB + row * 128 + ((c ^ (row & 7)) << 4));
            }
#pragma unroll
            for (int mi = 0; mi < 4; mi++) {
                mma_fp8(acc[mi][0], a[mi], &b[0][0]);
                mma_fp8(acc[mi][1], a[mi], &b[0][2]);
                mma_fp8(acc[mi][2], a[mi], &b[1][0]);
                mma_fp8(acc[mi][3], a[mi], &b[1][2]);
            }
        }
    };

    CP_WAIT(0);
    __syncthreads();   // tiles + bias + sdot visible

    compute(S_A0, S_B0);
#pragma unroll
    for (int a = 0; a < 4; a++)    // phase-0 operands are 64x larger
#pragma unroll
        for (int b = 0; b < 4; b++)
#pragma unroll
            for (int c = 0; c < 4; c++) acc[a][b][c] *= 0.015625f;
    compute(S_A1, S_B1);

    // ---- epilogue (true value = acc * S_in + bias) ----
    const int qr = lane >> 2;
    const int qc = (lane & 3) * 2;

    if (l < 2) {
        uint8_t* __restrict__ O = g_h8[outsel];
        float* __restrict__ ro_next = g_ro_all[l + 1];
        float colsum[4][2];
#pragma unroll
        for (int ni = 0; ni < 4; ni++) colsum[ni][0] = colsum[ni][1] = 0.0f;
#pragma unroll
        for (int mi = 0; mi < 4; mi++) {
            int r0 = bm + wm + mi * 16 + qr;
#pragma unroll
            for (int ni = 0; ni < 4; ni++) {
                int col = wn + ni * 8 + qc;
                float b0 = sbias[col], b1 = sbias[col + 1];
                float v0 = fmaxf(fmaf(acc[mi][ni][0], fin, b0), 0.f);
                float v1 = fmaxf(fmaf(acc[mi][ni][1], fin, b1), 0.f);
                float v2 = fmaxf(fmaf(acc[mi][ni][2], fin, b0), 0.f);
                float v3 = fmaxf(fmaf(acc[mi][ni][3], fin, b1), 0.f);
                if (r0 < n) {
                    *(uint16_t*)(O + (size_t)r0 * DIMX + col) =
                        pack_f8x2(v0 * inv_out, v1 * inv_out);
                    colsum[ni][0] += v0; colsum[ni][1] += v1;
                }
                if (r0 + 8 < n) {
                    *(uint16_t*)(O + (size_t)(r0 + 8) * DIMX + col) =
                        pack_f8x2(v2 * inv_out, v3 * inv_out);
                    colsum[ni][0] += v2; colsum[ni][1] += v3;
                }
            }
        }
#pragma unroll
        for (int ni = 0; ni < 4; ni++)
#pragma unroll
            for (int j = 0; j < 2; j++) {
                float v = colsum[ni][j];
                v += __shfl_xor_sync(0xffffffffu, v, 4);
                v += __shfl_xor_sync(0xffffffffu, v, 8);
                v += __shfl_xor_sync(0xffffffffu, v, 16);
                if (lane < 4)
                    atomicAdd(&ro_next[wn + ni * 8 + lane * 2 + j], v);
            }
    } else {
        // final layer: sigmoid head fused; no h store, no readout
#pragma unroll
        for (int mi = 0; mi < 4; mi++) {
            int rl = wm + mi * 16 + qr;
            int r0 = bm + rl;
            float dA0 = 0.f, dA1 = 0.f, dB0 = 0.f, dB1 = 0.f;
#pragma unroll
            for (int ni = 0; ni < 4; ni++) {
                int col = wn + ni * 8 + qc;
                float b0 = sbias[col], b1 = sbias[col + 1];
                float w0 = sow[col], w1 = sow[col + 1];
                float u0 = sow[128 + col], u1 = sow[128 + col + 1];
                float v0 = fmaxf(fmaf(acc[mi][ni][0], fin, b0), 0.f);
                float v1 = fmaxf(fmaf(acc[mi][ni][1], fin, b1), 0.f);
                float v2 = fmaxf(fmaf(acc[mi][ni][2], fin, b0), 0.f);
                float v3 = fmaxf(fmaf(acc[mi][ni][3], fin, b1), 0.f);
                dA0 += v0 * w0 + v1 * w1;
                dA1 += v0 * u0 + v1 * u1;
                dB0 += v2 * w0 + v3 * w1;
                dB1 += v2 * u0 + v3 * u1;
            }
            if (r0 < n) {
                atomicAdd(&sdot[rl * 2 + 0], dA0);
                atomicAdd(&sdot[rl * 2 + 1], dA1);
            }
            if (r0 + 8 < n) {
                atomicAdd(&sdot[(rl + 8) * 2 + 0], dB0);
                atomicAdd(&sdot[(rl + 8) * 2 + 1], dB1);
            }
        }
        __syncthreads();
        if (tid < 128) {
            int gm = bm + tid;
            if (gm < n) {
                float z0 = sdot[tid * 2 + 0] + ob[0];
                float z1 = sdot[tid * 2 + 1] + ob[1];
                float2 o;
                o.x = 1.0f / (1.0f + __expf(-z0));
                o.y = 1.0f / (1.0f + __expf(-z1));
                *(float2*)(out + (size_t)gm * 2) = o;
            }
        }
    }
}

// ================= launch =================

extern "C" void kernel_launch(void* const* d_in, const int* in_sizes, int n_in,
                              void* d_out, int out_size) {
    const float* x  = (const float*)d_in[0];
    const int* src  = (const int*)d_in[1];
    const int* dst  = (const int*)d_in[2];
    const float* Vw = (const float*)d_in[3];
    const float* Vb = (const float*)d_in[4];
    const float* Aw = (const float*)d_in[5];
    const float* Ab = (const float*)d_in[6];
    const float* Rw = (const float*)d_in[7];
    const float* Rb = (const float*)d_in[8];
    const float* ow = (const float*)d_in[9];
    const float* ob = (const float*)d_in[10];
    float* out = (float*)d_out;

    const int n = in_sizes[0] / DIMX;   // 50000
    const int e = in_sizes[1];          // 800000

    cudaFuncSetAttribute(gemm_mma_kernel,
                         cudaFuncAttributeMaxDynamicSharedMemorySize, GEMM_SMEM);

    int n2 = (n * DIMX) / 2;
    setup_kernel<<<(n2 + 255) / 256, 256>>>(x, Vw, Aw, dst, n2, n, e);

    int nb = (n + 1023) / 1024;
    scan1_kernel<<<nb, 1024>>>(n);
    scan3_kernel<<<nb, 1024>>>(n);
    scatter_kernel<<<(e + 255) / 256, 256>>>(src, dst, e);
    readout0_kernel<<<512, 64>>>(n);

    for (int l = 0; l < 3; l++) {
        int insel = l & 1;       // 0,1,0
        int outsel = insel ^ 1;  // 1,0,1
        agg_kernel<<<(n * 32 + 255) / 256, 256>>>(insel, n);
        bias_kernel<<<1, 1024>>>(Vb, Ab, Rb, Rw, l);
        gemm_mma_kernel<<<(n + 127) / 128, 256, GEMM_SMEM>>>(
            insel, outsel, l, n, ow, ob, out);
    }
}

// round 16
// speedup vs baseline: 1.5075x; 1.0200x over previous
#include <cuda_runtime.h>
#include <cuda_bf16.h>
#include <cuda_fp16.h>
#include <cstdint>

#define NN 50000
#define DIMX 128
#define NE 800000

// ---- scratch (static __device__ globals; zero-initialized at load) ----
__device__ uint8_t g_h8[2][NN * DIMX];     // ping-pong hidden states, e4m3 (h/S_l)
__device__ uint8_t g_agg8[NN * DIMX];      // aggregation, e4m3 (agg/(64*S_l))
__device__ uint8_t g_Wf8[3 * 2 * DIMX * DIMX];  // weights e4m3, pre-scaled x64
__device__ int   g_off[NN + 1];
__device__ int   g_cnt[NN];     // degree counters; invariant: zero at launch entry
__device__ int   g_srt[NE];
__device__ int   g_bsum[64];
__device__ float g_ro_all[4][DIMX];   // readout per layer (true units)
__device__ float g_bias[DIMX];        // combined bias for current layer
__device__ float g_scale[4];          // S_l (power of 2); S_0 = 1
__device__ float g_iscale[4];         // 1/S_l

// ================= helpers =================

__device__ __forceinline__ uint32_t smem_u32(const void* p) {
    uint32_t a;
    asm("{ .reg .u64 t; cvta.to.shared.u64 t, %1; cvt.u32.u64 %0, t; }"
        : "=r"(a) : "l"(p));
    return a;
}

__device__ __forceinline__ void ldm_x4(uint32_t* r, uint32_t addr) {
    asm volatile("ldmatrix.sync.aligned.m8n8.x4.shared.b16 {%0,%1,%2,%3}, [%4];"
                 : "=r"(r[0]), "=r"(r[1]), "=r"(r[2]), "=r"(r[3]) : "r"(addr));
}

__device__ __forceinline__ void mma_fp8(float* c, const uint32_t* a,
                                        const uint32_t* b) {
    asm volatile(
        "mma.sync.aligned.m16n8k32.row.col.f32.e4m3.e4m3.f32 "
        "{%0,%1,%2,%3}, {%4,%5,%6,%7}, {%8,%9}, {%0,%1,%2,%3};"
        : "+f"(c[0]), "+f"(c[1]), "+f"(c[2]), "+f"(c[3])
        : "r"(a[0]), "r"(a[1]), "r"(a[2]), "r"(a[3]), "r"(b[0]), "r"(b[1]));
}

__device__ __forceinline__ void cp16(uint32_t dst, const void* src) {
    asm volatile("cp.async.cg.shared.global [%0], [%1], 16;"
                 :: "r"(dst), "l"(src) : "memory");
}
__device__ __forceinline__ void cp16z(uint32_t dst, const void* src, int sz) {
    asm volatile("cp.async.cg.shared.global [%0], [%1], 16, %2;"
                 :: "r"(dst), "l"(src), "r"(sz) : "memory");
}
#define CP_COMMIT() asm volatile("cp.async.commit_group;" ::: "memory")
#define CP_WAIT(N)  asm volatile("cp.async.wait_group %0;" :: "n"(N) : "memory")

// pack two f32 into one e4m3x2 halfword (byte0 = lo)
__device__ __forceinline__ uint16_t pack_f8x2(float lo, float hi) {
    uint16_t r;
    asm("cvt.rn.satfinite.e4m3x2.f32 %0, %1, %2;" : "=h"(r) : "f"(hi), "f"(lo));
    return r;
}

// 2 e4m3 (in low 16 bits) -> half2
__device__ __forceinline__ __half2 f8x2_to_h2(uint16_t w) {
    uint32_t r;
    asm("cvt.rn.f16x2.e4m3x2 %0, %1;" : "=r"(r) : "h"(w));
    return *reinterpret_cast<__half2*>(&r);
}

// half2 -> e4m3x2 halfword
__device__ __forceinline__ uint16_t h2_to_f8x2(__half2 h) {
    uint16_t r;
    asm("cvt.rn.satfinite.e4m3x2.f16x2 %0, %1;"
        : "=h"(r) : "r"(*reinterpret_cast<uint32_t*>(&h)));
    return r;
}

// accumulate 4 e4m3 packed in u32 into two half2 accumulators
__device__ __forceinline__ void acc_f8x4(__half2& a0, __half2& a1, uint32_t w) {
    a0 = __hadd2(a0, f8x2_to_h2((uint16_t)(w & 0xffffu)));
    a1 = __hadd2(a1, f8x2_to_h2((uint16_t)(w >> 16)));
}

// ====== setup: x->fp8 + W->fp8 + hist (MLP-4) + zero ro + scale + g_off[n] ====

__global__ void setup_kernel(const float* __restrict__ x,
                             const float* __restrict__ Vw,
                             const float* __restrict__ Aw,
                             const int* __restrict__ dst,
                             int n2, int n, int e) {
    int i = blockIdx.x * blockDim.x + threadIdx.x;
    if (i < n2) {   // n2 = n*128/2 pairs; S_0 = 1
        float2 v = reinterpret_cast<const float2*>(x)[i];
        reinterpret_cast<uint16_t*>(g_h8[0])[i] = pack_f8x2(v.x, v.y);
    }
    if (i < 3 * 16384) {   // weight pairs, x64
        int el2 = i * 2;
        int l = el2 >> 15;
        int rem = el2 & 32767;
        int phase = rem >> 14;
        int el = rem & 16383;
        const float* W = phase ? Aw : Vw;
        float a = W[l * 16384 + el] * 64.0f;
        float b = W[l * 16384 + el + 1] * 64.0f;
        reinterpret_cast<uint16_t*>(g_Wf8)[i] = pack_f8x2(a, b);
    }
    int e4 = (e + 3) >> 2;
    if (i < e4) {   // 4 independent hist atomics per thread (coalesced loads)
#pragma unroll
        for (int k = 0; k < 4; k++) {
            int idx = i + k * e4;
            if (idx < e) atomicAdd(&g_cnt[dst[idx]], 1);
        }
    }
    if (i < 4 * DIMX) ((float*)g_ro_all)[i] = 0.0f;
    if (i == 0) { g_off[n] = e; g_scale[0] = 1.0f; g_iscale[0] = 1.0f; }
}

// ================= CSR build =================

__global__ void scan1_kernel(int n) {
    __shared__ int s[1024];
    int i = blockIdx.x * 1024 + threadIdx.x;
    int v = (i < n) ? g_cnt[i] : 0;
    s[threadIdx.x] = v;
    __syncthreads();
    for (int off = 1; off < 1024; off <<= 1) {
        int t = (threadIdx.x >= off) ? s[threadIdx.x - off] : 0;
        __syncthreads();
        s[threadIdx.x] += t;
        __syncthreads();
    }
    if (i < n) g_off[i] = s[threadIdx.x] - v;
    if (threadIdx.x == 1023) g_bsum[blockIdx.x] = s[1023];
}

__global__ void scan3_kernel(int n) {
    __shared__ int spre[2];
    int tid = threadIdx.x;
    if (tid < 64) {
        int v = (tid < blockIdx.x) ? g_bsum[tid] : 0;
#pragma unroll
        for (int o = 16; o; o >>= 1) v += __shfl_xor_sync(0xffffffffu, v, o);
        if ((tid & 31) == 0) spre[tid >> 5] = v;
    }
    __syncthreads();
    int pre = spre[0] + spre[1];
    int i = blockIdx.x * 1024 + tid;
    if (i < n) g_off[i] += pre;
}

// scatter: 4 independent edge chains per thread (MLP-4); countdown re-zeros cnt
__global__ void scatter_kernel(const int* __restrict__ src,
                               const int* __restrict__ dst, int e) {
    int i = blockIdx.x * blockDim.x + threadIdx.x;
    int e4 = (e + 3) >> 2;
    if (i >= e4) return;
#pragma unroll
    for (int k = 0; k < 4; k++) {
        int idx = i + k * e4;
        if (idx < e) {
            int d = dst[idx];
            int pos = g_off[d] + atomicAdd(&g_cnt[d], -1) - 1;
            g_srt[pos] = src[idx];
        }
    }
}

// ============ readout of layer-0 input (fp8, S_0=1) ============

__global__ void readout0_kernel(int n) {
    const uint8_t* __restrict__ h = g_h8[0];
    int j = threadIdx.x;  // 64 threads, 2 cols each
    float s0 = 0.0f, s1 = 0.0f;
    for (int i = blockIdx.x; i < n; i += gridDim.x) {
        uint16_t w = *(const uint16_t*)(h + (size_t)i * DIMX + j * 2);
        __half2 v = f8x2_to_h2(w);
        s0 += __low2float(v);
        s1 += __high2float(v);
    }
    atomicAdd(&g_ro_all[0][j * 2 + 0], s0);
    atomicAdd(&g_ro_all[0][j * 2 + 1], s1);
}

// ========== aggregation: warp per node, fp8 rows; block 0 also computes bias ==
// agg8[i] = (h8[i] + sum_{e} h8[srt[e]]) / 64
// block 0: bias = Vb+Ab+Rb + ro@Rw^T (coalesced), plus output scale for l+1.

__global__ void __launch_bounds__(256)
agg_kernel(int insel, int n, int l,
           const float* __restrict__ Vb, const float* __restrict__ Ab,
           const float* __restrict__ Rb, const float* __restrict__ Rw) {
    __shared__ float smax[8];
    int tid = threadIdx.x;

    if (blockIdx.x == 0) {
        // ---- bias for this layer (256 threads, 8 warps x 16 outputs) ----
        int wb = tid >> 5, lane = tid & 31;
        const float* __restrict__ ro = g_ro_all[l];
        float4 r4 = reinterpret_cast<const float4*>(ro)[lane];
        float mymax = 0.0f;
#pragma unroll
        for (int q = 0; q < 16; q++) {
            int j = wb * 16 + q;
            float4 w4 = reinterpret_cast<const float4*>(
                Rw + (size_t)l * 16384 + (size_t)j * DIMX)[lane];
            float s = w4.x * r4.x + w4.y * r4.y + w4.z * r4.z + w4.w * r4.w;
#pragma unroll
            for (int o = 16; o; o >>= 1)
                s += __shfl_xor_sync(0xffffffffu, s, o);
            if (lane == 0) {
                float b = s + Vb[l * DIMX + j] + Ab[l * DIMX + j]
                            + Rb[l * DIMX + j];
                g_bias[j] = b;
                mymax = fmaxf(mymax, fabsf(b));
            }
        }
        if (lane == 0) smax[wb] = mymax;
        __syncthreads();
        if (tid == 0) {
            float m = 0.0f;
#pragma unroll
            for (int i = 0; i < 8; i++) m = fmaxf(m, smax[i]);
            int eo = ((int)((__float_as_uint(m) >> 23) & 0xff)) - 127 + 4;
            if (eo < -60) eo = -60;
            if (eo > 60) eo = 60;
            g_scale[l + 1]  = __uint_as_float((uint32_t)(127 + eo) << 23);
            g_iscale[l + 1] = __uint_as_float((uint32_t)(127 - eo) << 23);
        }
    }

    // ---- node aggregation ----
    int w = (blockIdx.x * blockDim.x + tid) >> 5;
    if (w >= n) return;
    int lane = tid & 31;
    int c = lane & 7;    // 16B chunk within 128B row
    int p = lane >> 3;   // edge parity 0..3
    const uint4* __restrict__ h4 =
        reinterpret_cast<const uint4*>(g_h8[insel]);

    __half2 a[8];
#pragma unroll
    for (int k = 0; k < 8; k++) a[k] = __half2half2(__ushort_as_half(0));

    if (p == 0) {   // self row counted once
        uint4 v = h4[(size_t)w * 8 + c];
        acc_f8x4(a[0], a[1], v.x);
        acc_f8x4(a[2], a[3], v.y);
        acc_f8x4(a[4], a[5], v.z);
        acc_f8x4(a[6], a[7], v.w);
    }

    int beg = g_off[w], end = g_off[w + 1];
    int e = beg + p;
    for (; e + 12 < end; e += 16) {
        int r0 = g_srt[e];
        int r1 = g_srt[e + 4];
        int r2 = g_srt[e + 8];
        int r3 = g_srt[e + 12];
        uint4 v0 = h4[(size_t)r0 * 8 + c];
        uint4 v1 = h4[(size_t)r1 * 8 + c];
        uint4 v2 = h4[(size_t)r2 * 8 + c];
        uint4 v3 = h4[(size_t)r3 * 8 + c];
        acc_f8x4(a[0], a[1], v0.x); acc_f8x4(a[2], a[3], v0.y);
        acc_f8x4(a[4], a[5], v0.z); acc_f8x4(a[6], a[7], v0.w);
        acc_f8x4(a[0], a[1], v1.x); acc_f8x4(a[2], a[3], v1.y);
        acc_f8x4(a[4], a[5], v1.z); acc_f8x4(a[6], a[7], v1.w);
        acc_f8x4(a[0], a[1], v2.x); acc_f8x4(a[2], a[3], v2.y);
        acc_f8x4(a[4], a[5], v2.z); acc_f8x4(a[6], a[7], v2.w);
        acc_f8x4(a[0], a[1], v3.x); acc_f8x4(a[2], a[3], v3.y);
        acc_f8x4(a[4], a[5], v3.z); acc_f8x4(a[6], a[7], v3.w);
    }
    for (; e < end; e += 4) {
        int r0 = g_srt[e];
        uint4 v0 = h4[(size_t)r0 * 8 + c];
        acc_f8x4(a[0], a[1], v0.x); acc_f8x4(a[2], a[3], v0.y);
        acc_f8x4(a[4], a[5], v0.z); acc_f8x4(a[6], a[7], v0.w);
    }

    // combine 4 parity groups (lane bits 3,4)
#pragma unroll
    for (int k = 0; k < 8; k++) {
        uint32_t u = *reinterpret_cast<uint32_t*>(&a[k]);
        uint32_t u1 = __shfl_xor_sync(0xffffffffu, u, 8);
        a[k] = __hadd2(a[k], *reinterpret_cast<__half2*>(&u1));
        u = *reinterpret_cast<uint32_t*>(&a[k]);
        uint32_t u2 = __shfl_xor_sync(0xffffffffu, u, 16);
        a[k] = __hadd2(a[k], *reinterpret_cast<__half2*>(&u2));
    }

    if (p == 0) {
        const __half2 s64 = __float2half2_rn(0.015625f);   // exact 1/64
        uint16_t q[8];
#pragma unroll
        for (int k = 0; k < 8; k++) q[k] = h2_to_f8x2(__hmul2(a[k], s64));
        uint4 o;
        o.x = (uint32_t)q[0] | ((uint32_t)q[1] << 16);
        o.y = (uint32_t)q[2] | ((uint32_t)q[3] << 16);
        o.z = (uint32_t)q[4] | ((uint32_t)q[5] << 16);
        o.w = (uint32_t)q[6] | ((uint32_t)q[7] << 16);
        reinterpret_cast<uint4*>(g_agg8)[(size_t)w * 8 + c] = o;
    }
}

// ====== FP8 QMMA GEMM, all-fp8 operands direct cp.async; bias precomputed ====
// h_out = relu([h|agg] @ [Vw;Aw]^T + bias); scale chain via g_scale/g_iscale.
// smem: A0 16K | A1 16K | B0 16K | B1 16K | bias | dot | ow

#define S_A0   0
#define S_A1   16384
#define S_B0   32768
#define S_B1   49152
#define S_BIAS 65536
#define S_DOT  66048
#define S_OW   67072
#define GEMM_SMEM 68096

__global__ void __launch_bounds__(256, 2)
gemm_mma_kernel(int insel, int outsel, int l, int n,
                const float* __restrict__ ow, const float* __restrict__ ob,
                float* __restrict__ out) {
    extern __shared__ char smem[];
    float* sbias = (float*)(smem + S_BIAS);
    float* sdot  = (float*)(smem + S_DOT);
    float* sow   = (float*)(smem + S_OW);
    const int tid = threadIdx.x;
    const int wid = tid >> 5, lane = tid & 31;
    const int bm = blockIdx.x * 128;
    const int wm = (wid & 1) * 64;
    const int wn = (wid >> 1) * 32;
    const uint32_t sbase = smem_u32(smem);

    const float fin = g_scale[l];                       // S_in (power of 2)
    const float inv_out = (l < 2) ? g_iscale[l + 1] : 1.0f;

    // ---- prefetch all 4 fp8 tiles (16KB each) ----
    const uint8_t* __restrict__ A0 = g_h8[insel];
    const uint8_t* __restrict__ A1 = g_agg8;
    const uint8_t* __restrict__ Wf8 = g_Wf8 + (size_t)l * 32768;
#pragma unroll
    for (int t = 0; t < 4; t++) {
        int idx = tid + t * 256;       // 0..1023 per tile
        int row = idx >> 3, cc = idx & 7;
        uint32_t so = (uint32_t)(row * 128 + ((cc ^ (row & 7)) << 4));
        int gm = bm + row;
        int gmc = gm < n ? gm : 0;
        int sz = gm < n ? 16 : 0;
        cp16z(sbase + S_A0 + so, A0 + (size_t)gmc * DIMX + cc * 16, sz);
        cp16z(sbase + S_A1 + so, A1 + (size_t)gmc * DIMX + cc * 16, sz);
        cp16(sbase + S_B0 + so, Wf8 + row * 128 + cc * 16);
        cp16(sbase + S_B1 + so, Wf8 + 16384 + row * 128 + cc * 16);
    }
    CP_COMMIT();

    // bias: precomputed per layer, one coalesced load
    if (tid < 128) sbias[tid] = g_bias[tid];
    if (l == 2) {
        sdot[tid] = 0.0f;
        sow[tid] = ow[tid];
    }

    float acc[4][4][4];
#pragma unroll
    for (int a = 0; a < 4; a++)
#pragma unroll
        for (int b = 0; b < 4; b++)
#pragma unroll
            for (int c = 0; c < 4; c++) acc[a][b][c] = 0.0f;

    auto compute = [&](int aoff, int boff) {
        const uint32_t sA = sbase + aoff;
        const uint32_t sB = sbase + boff;
#pragma unroll
        for (int ks = 0; ks < 4; ks++) {       // K=32 fp8 per step
            const int kc = ks * 2;
            uint32_t a[4][4], b[2][4];
#pragma unroll
            for (int mi = 0; mi < 4; mi++) {
                int row = wm + mi * 16 + (lane & 15);
                int c = kc + (lane >> 4);
                ldm_x4(a[mi], sA + row * 128 + ((c ^ (row & 7)) << 4));
            }
#pragma unroll
            for (int nj = 0; nj < 2; nj++) {
                int row = wn + nj * 16 + ((lane >> 4) << 3) + (lane & 7);
                int c = kc + ((lane >> 3) & 1);
                ldm_x4(b[nj], sB + row * 128 + ((c ^ (row & 7)) << 4));
            }
#pragma unroll
            for (int mi = 0; mi < 4; mi++) {
                mma_fp8(acc[mi][0], a[mi], &b[0][0]);
                mma_fp8(acc[mi][1], a[mi], &b[0][2]);
                mma_fp8(acc[mi][2], a[mi], &b[1][0]);
                mma_fp8(acc[mi][3], a[mi], &b[1][2]);
            }
        }
    };

    CP_WAIT(0);
    __syncthreads();   // tiles + bias + sdot visible

    compute(S_A0, S_B0);
#pragma unroll
    for (int a = 0; a < 4; a++)    // phase-0 operands are 64x larger
#pragma unroll
        for (int b = 0; b < 4; b++)
#pragma unroll
            for (int c = 0; c < 4; c++) acc[a][b][c] *= 0.015625f;
    compute(S_A1, S_B1);

    // ---- epilogue (true value = acc * S_in + bias) ----
    const int qr = lane >> 2;
    const int qc = (lane & 3) * 2;

    if (l < 2) {
        uint8_t* __restrict__ O = g_h8[outsel];
        float* __restrict__ ro_next = g_ro_all[l + 1];
        float colsum[4][2];
#pragma unroll
        for (int ni = 0; ni < 4; ni++) colsum[ni][0] = colsum[ni][1] = 0.0f;
#pragma unroll
        for (int mi = 0; mi < 4; mi++) {
            int r0 = bm + wm + mi * 16 + qr;
#pragma unroll
            for (int ni = 0; ni < 4; ni++) {
                int col = wn + ni * 8 + qc;
                float b0 = sbias[col], b1 = sbias[col + 1];
                float v0 = fmaxf(fmaf(acc[mi][ni][0], fin, b0), 0.f);
                float v1 = fmaxf(fmaf(acc[mi][ni][1], fin, b1), 0.f);
                float v2 = fmaxf(fmaf(acc[mi][ni][2], fin, b0), 0.f);
                float v3 = fmaxf(fmaf(acc[mi][ni][3], fin, b1), 0.f);
                if (r0 < n) {
                    *(uint16_t*)(O + (size_t)r0 * DIMX + col) =
                        pack_f8x2(v0 * inv_out, v1 * inv_out);
                    colsum[ni][0] += v0; colsum[ni][1] += v1;
                }
                if (r0 + 8 < n) {
                    *(uint16_t*)(O + (size_t)(r0 + 8) * DIMX + col) =
                        pack_f8x2(v2 * inv_out, v3 * inv_out);
                    colsum[ni][0] += v2; colsum[ni][1] += v3;
                }
            }
        }
#pragma unroll
        for (int ni = 0; ni < 4; ni++)
#pragma unroll
            for (int j = 0; j < 2; j++) {
                float v = colsum[ni][j];
                v += __shfl_xor_sync(0xffffffffu, v, 4);
                v += __shfl_xor_sync(0xffffffffu, v, 8);
                v += __shfl_xor_sync(0xffffffffu, v, 16);
                if (lane < 4)
                    atomicAdd(&ro_next[wn + ni * 8 + lane * 2 + j], v);
            }
    } else {
        // final layer: sigmoid head fused; no h store, no readout
#pragma unroll
        for (int mi = 0; mi < 4; mi++) {
            int rl = wm + mi * 16 + qr;
            int r0 = bm + rl;
            float dA0 = 0.f, dA1 = 0.f, dB0 = 0.f, dB1 = 0.f;
#pragma unroll
            for (int ni = 0; ni < 4; ni++) {
                int col = wn + ni * 8 + qc;
                float b0 = sbias[col], b1 = sbias[col + 1];
                float w0 = sow[col], w1 = sow[col + 1];
                float u0 = sow[128 + col], u1 = sow[128 + col + 1];
                float v0 = fmaxf(fmaf(acc[mi][ni][0], fin, b0), 0.f);
                float v1 = fmaxf(fmaf(acc[mi][ni][1], fin, b1), 0.f);
                float v2 = fmaxf(fmaf(acc[mi][ni][2], fin, b0), 0.f);
                float v3 = fmaxf(fmaf(acc[mi][ni][3], fin, b1), 0.f);
                dA0 += v0 * w0 + v1 * w1;
                dA1 += v0 * u0 + v1 * u1;
                dB0 += v2 * w0 + v3 * w1;
                dB1 += v2 * u0 + v3 * u1;
            }
            if (r0 < n) {
                atomicAdd(&sdot[rl * 2 + 0], dA0);
                atomicAdd(&sdot[rl * 2 + 1], dA1);
            }
            if (r0 + 8 < n) {
                atomicAdd(&sdot[(rl + 8) * 2 + 0], dB0);
                atomicAdd(&sdot[(rl + 8) * 2 + 1], dB1);
            }
        }
        __syncthreads();
        if (tid < 128) {
            int gm = bm + tid;
            if (gm < n) {
                float z0 = sdot[tid * 2 + 0] + ob[0];
                float z1 = sdot[tid * 2 + 1] + ob[1];
                float2 o;
                o.x = 1.0f / (1.0f + __expf(-z0));
                o.y = 1.0f / (1.0f + __expf(-z1));
                *(float2*)(out + (size_t)gm * 2) = o;
            }
        }
    }
}

// ================= launch =================

extern "C" void kernel_launch(void* const* d_in, const int* in_sizes, int n_in,
                              void* d_out, int out_size) {
    const float* x  = (const float*)d_in[0];
    const int* src  = (const int*)d_in[1];
    const int* dst  = (const int*)d_in[2];
    const float* Vw = (const float*)d_in[3];
    const float* Vb = (const float*)d_in[4];
    const float* Aw = (const float*)d_in[5];
    const float* Ab = (const float*)d_in[6];
    const float* Rw = (const float*)d_in[7];
    const float* Rb = (const float*)d_in[8];
    const float* ow = (const float*)d_in[9];
    const float* ob = (const float*)d_in[10];
    float* out = (float*)d_out;

    const int n = in_sizes[0] / DIMX;   // 50000
    const int e = in_sizes[1];          // 800000

    cudaFuncSetAttribute(gemm_mma_kernel,
                         cudaFuncAttributeMaxDynamicSharedMemorySize, GEMM_SMEM);

    int n2 = (n * DIMX) / 2;
    setup_kernel<<<(n2 + 255) / 256, 256>>>(x, Vw, Aw, dst, n2, n, e);

    int nb = (n + 1023) / 1024;
    int e4 = (e + 3) / 4;
    scan1_kernel<<<nb, 1024>>>(n);
    scan3_kernel<<<nb, 1024>>>(n);
    scatter_kernel<<<(e4 + 255) / 256, 256>>>(src, dst, e);
    readout0_kernel<<<512, 64>>>(n);

    for (int l = 0; l < 3; l++) {
        int insel = l & 1;       // 0,1,0
        int outsel = insel ^ 1;  // 1,0,1
        agg_kernel<<<(n * 32 + 255) / 256, 256>>>(insel, n, l, Vb, Ab, Rb, Rw);
        gemm_mma_kernel<<<(n + 127) / 128, 256, GEMM_SMEM>>>(
            insel, outsel, l, n, ow, ob, out);
    }
}